// round 16
// baseline (speedup 1.0000x reference)
#include <cuda_runtime.h>
#include <cstdint>

// Problem constants (fixed shapes per reference)
#define B_    16
#define CIN_  128
#define COUT_ 3
#define WDIM_ 512
#define HW_   65536           // 256*256
#define HW4_  16384           // HW/4 (float4 granularity)

#define TILE_P  256           // float4 pixels per block (1 per thread)
#define STAGES  4
#define CH      2             // channels per chunk
#define NCHUNK  (CIN_ / CH)   // 64

// Scratch: coef[b][o][i] = style[b][i] * weight[o][i]
__device__ float g_coef[B_ * COUT_ * CIN_];

// ---------------------------------------------------------------------------
// Kernel 1: one WARP per (b,c) dot product (2048 warps total).
// ---------------------------------------------------------------------------
__global__ __launch_bounds__(256)
void coef_kernel(const float* __restrict__ w,
                 const float* __restrict__ weight,
                 const float* __restrict__ affine_w,
                 const float* __restrict__ affine_b) {
    const int warp = (blockIdx.x * blockDim.x + threadIdx.x) >> 5;
    const int lane = threadIdx.x & 31;
    const int b = warp >> 7;
    const int c = warp & 127;

    const float4* wb = reinterpret_cast<const float4*>(w + (size_t)b * WDIM_);
    const float4* aw = reinterpret_cast<const float4*>(affine_w + (size_t)c * WDIM_);

    float s = 0.0f;
    #pragma unroll
    for (int k = 0; k < 4; k++) {
        float4 a = aw[lane + k * 32];
        float4 v = wb[lane + k * 32];
        s += a.x * v.x + a.y * v.y + a.z * v.z + a.w * v.w;
    }
    #pragma unroll
    for (int off = 16; off > 0; off >>= 1)
        s += __shfl_down_sync(0xFFFFFFFFu, s, off);

    if (lane == 0) {
        s += affine_b[c];
        #pragma unroll
        for (int o = 0; o < COUT_; o++)
            g_coef[((size_t)b * COUT_ + o) * CIN_ + c] = s * weight[o * CIN_ + c];
    }
}

// ---------------------------------------------------------------------------
// Kernel 2: cp.async-pipelined streaming reduce.
// Each thread owns one float4 pixel; channels stream through a 4-stage,
// 2-channel-per-chunk cp.async pipeline. Thread t loads exactly the data
// thread t consumes -> no __syncthreads in the main loop; wait_group orders
// each thread's own async copies. In-flight bytes live in SMEM, not RF.
// grid = (HW4_/TILE_P, B_) = (64, 16), block = 256.
// ---------------------------------------------------------------------------
__global__ void __launch_bounds__(256, 6)
torgb_kernel(const float* __restrict__ x,
             const float* __restrict__ bias,
             float* __restrict__ out) {
    const int b  = blockIdx.y;
    const int t  = threadIdx.x;
    const int p0 = blockIdx.x * TILE_P;

    __shared__ float4 buf[STAGES][CH][TILE_P];   // 32 KB
    __shared__ float  sc[COUT_ * CIN_];          // 1.5 KB

    for (int i = t; i < COUT_ * CIN_; i += 256)
        sc[i] = g_coef[(size_t)b * COUT_ * CIN_ + i];
    __syncthreads();   // only barrier in the kernel (coefs are block-shared)

    const float4* xb = reinterpret_cast<const float4*>(x)
                       + (size_t)b * CIN_ * HW4_ + p0 + t;

    const uint32_t buf_base =
        (uint32_t)__cvta_generic_to_shared(&buf[0][0][0]);
    const uint32_t dst_t = buf_base + (uint32_t)t * 16u;

    // issue chunk k: channels 2k, 2k+1 into stage k & 3
    #define ISSUE_CHUNK(k)                                                     \
        do {                                                                   \
            const int s_ = (k) & (STAGES - 1);                                 \
            const float4* src0_ = xb + (size_t)(2 * (k)) * HW4_;               \
            const float4* src1_ = src0_ + HW4_;                                \
            uint32_t d0_ = dst_t + (uint32_t)(s_ * CH + 0) * (TILE_P * 16);    \
            uint32_t d1_ = dst_t + (uint32_t)(s_ * CH + 1) * (TILE_P * 16);    \
            asm volatile("cp.async.cg.shared.global [%0], [%1], 16;"           \
                         :: "r"(d0_), "l"(src0_));                             \
            asm volatile("cp.async.cg.shared.global [%0], [%1], 16;"           \
                         :: "r"(d1_), "l"(src1_));                             \
        } while (0)

    // prologue: fill STAGES-1 stages
    ISSUE_CHUNK(0);
    asm volatile("cp.async.commit_group;" ::: "memory");
    ISSUE_CHUNK(1);
    asm volatile("cp.async.commit_group;" ::: "memory");
    ISSUE_CHUNK(2);
    asm volatile("cp.async.commit_group;" ::: "memory");

    float4 a0 = make_float4(0.f, 0.f, 0.f, 0.f);
    float4 a1 = a0, a2 = a0;

    #pragma unroll 4
    for (int k = 0; k < NCHUNK; k++) {
        // chunk k's group is complete when <=2 newer groups remain pending
        asm volatile("cp.async.wait_group 2;" ::: "memory");

        const int s = k & (STAGES - 1);
        float4 v0 = buf[s][0][t];
        float4 v1 = buf[s][1][t];

        const int ch = 2 * k;
        const float c00 = sc[0 * CIN_ + ch], c01 = sc[0 * CIN_ + ch + 1];
        const float c10 = sc[1 * CIN_ + ch], c11 = sc[1 * CIN_ + ch + 1];
        const float c20 = sc[2 * CIN_ + ch], c21 = sc[2 * CIN_ + ch + 1];

        a0.x += v0.x * c00; a0.y += v0.y * c00; a0.z += v0.z * c00; a0.w += v0.w * c00;
        a1.x += v0.x * c10; a1.y += v0.y * c10; a1.z += v0.z * c10; a1.w += v0.w * c10;
        a2.x += v0.x * c20; a2.y += v0.y * c20; a2.z += v0.z * c20; a2.w += v0.w * c20;

        a0.x += v1.x * c01; a0.y += v1.y * c01; a0.z += v1.z * c01; a0.w += v1.w * c01;
        a1.x += v1.x * c11; a1.y += v1.y * c11; a1.z += v1.z * c11; a1.w += v1.w * c11;
        a2.x += v1.x * c21; a2.y += v1.y * c21; a2.z += v1.z * c21; a2.w += v1.w * c21;

        if (k + STAGES - 1 < NCHUNK) ISSUE_CHUNK(k + STAGES - 1);
        // always commit (possibly-empty group) to keep wait_group counting aligned
        asm volatile("cp.async.commit_group;" ::: "memory");
    }
    #undef ISSUE_CHUNK

    const float b0 = bias[0], b1 = bias[1], b2 = bias[2];
    a0.x += b0; a0.y += b0; a0.z += b0; a0.w += b0;
    a1.x += b1; a1.y += b1; a1.z += b1; a1.w += b1;
    a2.x += b2; a2.y += b2; a2.z += b2; a2.w += b2;

    float4* ob = reinterpret_cast<float4*>(out)
                 + (size_t)b * COUT_ * HW4_ + p0 + t;
    __stcs(&ob[0 * HW4_], a0);
    __stcs(&ob[1 * HW4_], a1);
    __stcs(&ob[2 * HW4_], a2);
}

// ---------------------------------------------------------------------------
// Launch. Inputs in metadata order: x, w, weight, bias, affine_w, affine_b
// ---------------------------------------------------------------------------
extern "C" void kernel_launch(void* const* d_in, const int* in_sizes, int n_in,
                              void* d_out, int out_size) {
    const float* x        = (const float*)d_in[0];
    const float* w        = (const float*)d_in[1];
    const float* weight   = (const float*)d_in[2];
    const float* bias     = (const float*)d_in[3];
    const float* affine_w = (const float*)d_in[4];
    const float* affine_b = (const float*)d_in[5];
    float* out = (float*)d_out;

    coef_kernel<<<256, 256>>>(w, weight, affine_w, affine_b);

    dim3 grid(HW4_ / TILE_P, B_);
    torgb_kernel<<<grid, 256>>>(x, bias, out);
}

// round 17
// speedup vs baseline: 1.1195x; 1.1195x over previous
#include <cuda_runtime.h>

// Problem constants (fixed shapes per reference)
#define B_    16
#define CIN_  128
#define COUT_ 3
#define WDIM_ 512
#define HW_   65536           // 256*256
#define HW4_  16384           // HW/4 (float4 granularity)

// Scratch: coef[b][o][i] = style[b][i] * weight[o][i]
__device__ float g_coef[B_ * COUT_ * CIN_];

// ---------------------------------------------------------------------------
// Kernel 1: one WARP per (b,c) dot product (2048 warps total).
// ---------------------------------------------------------------------------
__global__ __launch_bounds__(256)
void coef_kernel(const float* __restrict__ w,
                 const float* __restrict__ weight,
                 const float* __restrict__ affine_w,
                 const float* __restrict__ affine_b) {
    const int warp = (blockIdx.x * blockDim.x + threadIdx.x) >> 5;
    const int lane = threadIdx.x & 31;
    const int b = warp >> 7;        // warp / 128
    const int c = warp & 127;       // warp % 128

    const float4* wb = reinterpret_cast<const float4*>(w + (size_t)b * WDIM_);
    const float4* aw = reinterpret_cast<const float4*>(affine_w + (size_t)c * WDIM_);

    float s = 0.0f;
    #pragma unroll
    for (int k = 0; k < 4; k++) {
        float4 a = aw[lane + k * 32];
        float4 v = wb[lane + k * 32];
        s += a.x * v.x + a.y * v.y + a.z * v.z + a.w * v.w;
    }
    #pragma unroll
    for (int off = 16; off > 0; off >>= 1)
        s += __shfl_down_sync(0xFFFFFFFFu, s, off);

    if (lane == 0) {
        s += affine_b[c];
        #pragma unroll
        for (int o = 0; o < COUT_; o++)
            g_coef[((size_t)b * COUT_ + o) * CIN_ + c] = s * weight[o * CIN_ + c];
    }
}

// ---------------------------------------------------------------------------
// Kernel 2 (streaming, plain-LDG — proven best structure from R15):
// out[b,o,hw] = sum_i x[b,i,hw]*coef[b,o,i] + bias[o]
// Channel-split (64 ch per thread); __launch_bounds__(256,8) -> 32 regs,
// 8 blocks/SM = 64 warps/SM (100% theoretical occupancy).
// grid = (HW4_/128, B_) = (128, 16), block = 256.
// ---------------------------------------------------------------------------
__global__ void __launch_bounds__(256, 8)
torgb_kernel(const float* __restrict__ x,
             const float* __restrict__ bias,
             float* __restrict__ out) {
    const int b    = blockIdx.y;
    const int tid  = threadIdx.x;
    const int half = tid >> 7;          // 0 or 1
    const int lp   = tid & 127;         // local pixel-group
    const int p    = blockIdx.x * 128 + lp;

    __shared__ float sc[COUT_ * CIN_];              // 384 coefs for this batch
    __shared__ float part[128][13];                 // 12 partials + pad

    for (int t = tid; t < COUT_ * CIN_; t += 256)
        sc[t] = g_coef[(size_t)b * COUT_ * CIN_ + t];
    __syncthreads();

    const float4* xb = reinterpret_cast<const float4*>(x)
                       + ((size_t)b * CIN_ + half * 64) * HW4_ + p;

    float4 a0 = make_float4(0.f, 0.f, 0.f, 0.f);
    float4 a1 = a0, a2 = a0;

    const int cbase = half * 64;
    #pragma unroll 4
    for (int i = 0; i < 64; i++) {
        float4 v = __ldcs(&xb[(size_t)i * HW4_]);
        const float c0 = sc[0 * CIN_ + cbase + i];
        const float c1 = sc[1 * CIN_ + cbase + i];
        const float c2 = sc[2 * CIN_ + cbase + i];
        a0.x += v.x * c0; a0.y += v.y * c0; a0.z += v.z * c0; a0.w += v.w * c0;
        a1.x += v.x * c1; a1.y += v.y * c1; a1.z += v.z * c1; a1.w += v.w * c1;
        a2.x += v.x * c2; a2.y += v.y * c2; a2.z += v.z * c2; a2.w += v.w * c2;
    }

    if (half == 1) {
        part[lp][0] = a0.x; part[lp][1]  = a0.y; part[lp][2]  = a0.z; part[lp][3]  = a0.w;
        part[lp][4] = a1.x; part[lp][5]  = a1.y; part[lp][6]  = a1.z; part[lp][7]  = a1.w;
        part[lp][8] = a2.x; part[lp][9]  = a2.y; part[lp][10] = a2.z; part[lp][11] = a2.w;
    }
    __syncthreads();

    if (half == 0) {
        const float b0 = bias[0], b1 = bias[1], b2 = bias[2];
        a0.x += part[lp][0] + b0; a0.y += part[lp][1]  + b0;
        a0.z += part[lp][2] + b0; a0.w += part[lp][3]  + b0;
        a1.x += part[lp][4] + b1; a1.y += part[lp][5]  + b1;
        a1.z += part[lp][6] + b1; a1.w += part[lp][7]  + b1;
        a2.x += part[lp][8] + b2; a2.y += part[lp][9]  + b2;
        a2.z += part[lp][10]+ b2; a2.w += part[lp][11] + b2;

        float4* ob = reinterpret_cast<float4*>(out)
                     + (size_t)b * COUT_ * HW4_ + p;
        __stcs(&ob[0 * HW4_], a0);
        __stcs(&ob[1 * HW4_], a1);
        __stcs(&ob[2 * HW4_], a2);
    }
}

// ---------------------------------------------------------------------------
// Launch. Inputs in metadata order: x, w, weight, bias, affine_w, affine_b
// ---------------------------------------------------------------------------
extern "C" void kernel_launch(void* const* d_in, const int* in_sizes, int n_in,
                              void* d_out, int out_size) {
    const float* x        = (const float*)d_in[0];
    const float* w        = (const float*)d_in[1];
    const float* weight   = (const float*)d_in[2];
    const float* bias     = (const float*)d_in[3];
    const float* affine_w = (const float*)d_in[4];
    const float* affine_b = (const float*)d_in[5];
    float* out = (float*)d_out;

    coef_kernel<<<256, 256>>>(w, weight, affine_w, affine_b);

    dim3 grid(HW4_ / 128, B_);
    torgb_kernel<<<grid, 256>>>(x, bias, out);
}